// round 15
// baseline (speedup 1.0000x reference)
#include <cuda_runtime.h>
#include <cuda_fp16.h>
#include <cstdint>
#include <cstddef>

#define USERS 50000
#define ITEMS 50000
#define NTOT  100000
#define DIM   128
#define EMAX  1700000
#define SCAN_BLOCK 1024
#define NB_MAX 512
#define NSEG  (NTOT + 1)

// ---------------- scratch (device globals; allocation-free) ----------------
__device__ float g_tmpA  [(size_t)NTOT * DIM];   // GEMM L0/L1
__device__ float g_tmpB  [(size_t)NTOT * DIM];   // GEMM L2/L3

// fp16 tables (16B-aligned for uint4 loads)
__device__ __align__(16) __half g_h_u     [(size_t)USERS * DIM];
__device__ __align__(16) __half g_h_i     [(size_t)ITEMS * DIM];
__device__ __align__(16) __half g_h_C     [(size_t)ITEMS * DIM];   // l2(allID)+l2(allFeat)
__device__ __align__(16) __half g_h_P     [(size_t)NTOT * DIM];    // Id+Ft
__device__ __align__(16) __half g_h_R     [(size_t)NTOT * DIM];    // IdAdj+FtAdj
__device__ __align__(16) __half g_h_modal [(size_t)NTOT * DIM];
__device__ __align__(16) __half g_h_A     [(size_t)NTOT * DIM];

// batched CSR: seg0 = adj, seg1 = id+ft merged
__device__ float2 g_cv_all [3 * EMAX];
__device__ int    g_rp     [2 * NSEG];
__device__ int    g_counts [2 * NSEG];
__device__ int    g_offs   [2 * NSEG];
__device__ int    g_bsums  [NB_MAX];

// ---------------- small utility kernels ----------------
__global__ void zero_int_kernel(int* __restrict__ p, int n) {
    int i = blockIdx.x * blockDim.x + threadIdx.x;
    if (i < n) p[i] = 0;
}

// both embedding tables -> fp16 in one launch
__global__ void f2h2_kernel(const float4* __restrict__ inU, const float4* __restrict__ inI,
                            uint2* __restrict__ outU, uint2* __restrict__ outI, int n4each) {
    int i = blockIdx.x * blockDim.x + threadIdx.x;
    if (i >= 2 * n4each) return;
    const float4* in = (i < n4each) ? inU : inI;
    uint2* o = (i < n4each) ? outU : outI;
    int j = (i < n4each) ? i : i - n4each;
    float4 v = in[j];
    __half2 h0 = __floats2half2_rn(v.x, v.y);
    __half2 h1 = __floats2half2_rn(v.z, v.w);
    uint2 r;
    r.x = *reinterpret_cast<uint32_t*>(&h0);
    r.y = *reinterpret_cast<uint32_t*>(&h1);
    o[j] = r;
}

// ---------------- batched counting sort (2 segments: adj | id+ft merged) ------------
__global__ void hist3_kernel(const int* __restrict__ r0, const int* __restrict__ r1,
                             const int* __restrict__ r2, int n0, int n1, int n2,
                             int* __restrict__ counts) {
    int i = blockIdx.x * blockDim.x + threadIdx.x;
    int nt = n0 + n1 + n2;
    if (i >= nt) return;
    int row, seg;
    if (i < n0)            { seg = 0; row = r0[i]; }
    else if (i < n0 + n1)  { seg = 1; row = r1[i - n0]; }
    else                   { seg = 1; row = r2[i - n0 - n1]; }   // merged with id
    atomicAdd(&counts[seg * NSEG + row], 1);
}

__global__ void scan1_kernel(const int* __restrict__ counts, int* __restrict__ rowptr,
                             int* __restrict__ bsums, int n) {
    __shared__ int sh[SCAN_BLOCK];
    int g = blockIdx.x * SCAN_BLOCK + threadIdx.x;
    int v = (g < n) ? counts[g] : 0;
    sh[threadIdx.x] = v;
    __syncthreads();
    for (int off = 1; off < SCAN_BLOCK; off <<= 1) {
        int t = (threadIdx.x >= off) ? sh[threadIdx.x - off] : 0;
        __syncthreads();
        sh[threadIdx.x] += t;
        __syncthreads();
    }
    if (g < n) rowptr[g] = sh[threadIdx.x] - v;   // exclusive
    if (threadIdx.x == SCAN_BLOCK - 1) bsums[blockIdx.x] = sh[threadIdx.x];
}

__global__ void scan2_kernel(int* __restrict__ bsums, int nb) {
    __shared__ int sh[NB_MAX];
    int v = (threadIdx.x < nb) ? bsums[threadIdx.x] : 0;
    sh[threadIdx.x] = v;
    __syncthreads();
    for (int off = 1; off < NB_MAX; off <<= 1) {
        int t = (threadIdx.x >= off) ? sh[threadIdx.x - off] : 0;
        __syncthreads();
        sh[threadIdx.x] += t;
        __syncthreads();
    }
    if (threadIdx.x < nb) bsums[threadIdx.x] = sh[threadIdx.x] - v;  // exclusive
}

__global__ void scan3_kernel(int* __restrict__ rowptr, const int* __restrict__ bsums,
                             int* __restrict__ offs, int n) {
    int g = blockIdx.x * SCAN_BLOCK + threadIdx.x;
    if (g < n) {
        int v = rowptr[g] + bsums[blockIdx.x];
        rowptr[g] = v;
        offs[g] = v;
    }
}

__global__ void scatter3_kernel(const int* __restrict__ r0, const int* __restrict__ c0, const float* __restrict__ v0,
                                const int* __restrict__ r1, const int* __restrict__ c1, const float* __restrict__ v1,
                                const int* __restrict__ r2, const int* __restrict__ c2, const float* __restrict__ v2,
                                int n0, int n1, int n2,
                                int* __restrict__ offs, float2* __restrict__ cv) {
    int i = blockIdx.x * blockDim.x + threadIdx.x;
    int nt = n0 + n1 + n2;
    if (i >= nt) return;
    int row, seg, col; float val;
    if (i < n0)           { seg = 0; int j = i;            row = r0[j]; col = c0[j]; val = v0[j]; }
    else if (i < n0 + n1) { seg = 1; int j = i - n0;       row = r1[j]; col = c1[j]; val = v1[j]; }
    else                  { seg = 1; int j = i - n0 - n1;  row = r2[j]; col = c2[j]; val = v2[j]; }
    int pos = atomicAdd(&offs[seg * NSEG + row], 1);
    cv[pos] = make_float2(__int_as_float(col), val);
}

// ---------------- tf32 tensor-core GEMM with 2-stage cp.async double buffering --------
__device__ __forceinline__ void mma_tf32(float c[4], uint32_t a0, uint32_t a1,
                                         uint32_t a2, uint32_t a3,
                                         uint32_t b0, uint32_t b1) {
    asm volatile(
        "mma.sync.aligned.m16n8k8.row.col.f32.tf32.tf32.f32 "
        "{%0,%1,%2,%3}, {%4,%5,%6,%7}, {%8,%9}, {%0,%1,%2,%3};"
        : "+f"(c[0]), "+f"(c[1]), "+f"(c[2]), "+f"(c[3])
        : "r"(a0), "r"(a1), "r"(a2), "r"(a3), "r"(b0), "r"(b1));
}

__device__ __forceinline__ void cp_async16(uint32_t smem_addr, const void* gsrc, int src_bytes) {
    asm volatile("cp.async.cg.shared.global [%0], [%1], 16, %2;"
                 :: "r"(smem_addr), "l"(gsrc), "r"(src_bytes));
}
__device__ __forceinline__ void cp_commit() {
    asm volatile("cp.async.commit_group;");
}
template <int N>
__device__ __forceinline__ void cp_wait() {
    asm volatile("cp.async.wait_group %0;" :: "n"(N));
}

#define AS_STRIDE 36
#define BS_STRIDE 132
#define AS_WORDS (128 * AS_STRIDE)
#define BS_WORDS (32 * BS_STRIDE)
#define GEMM_SMEM_WORDS (2 * (AS_WORDS + BS_WORDS))
#define GEMM_SMEM_BYTES (GEMM_SMEM_WORDS * 4)

__global__ __launch_bounds__(256, 2) void gemm4_kernel(
    const float* __restrict__ A0, const float* __restrict__ A1,
    const float* __restrict__ A2, const float* __restrict__ A3,
    const float* __restrict__ B0, const float* __restrict__ B1,
    const float* __restrict__ B2, const float* __restrict__ B3,
    float* __restrict__ L0, float* __restrict__ L1,
    float* __restrict__ L2, float* __restrict__ L3)
{
    extern __shared__ uint32_t smem[];
    uint32_t* As[2] = { smem, smem + AS_WORDS };
    uint32_t* Bs[2] = { smem + 2 * AS_WORDS, smem + 2 * AS_WORDS + BS_WORDS };

    int g = blockIdx.y;
    const float* A = (g == 0) ? A0 : (g == 1) ? A1 : (g == 2) ? A2 : A3;
    const float* B = (g == 0) ? B0 : (g == 1) ? B1 : (g == 2) ? B2 : B3;
    float*       L = (g == 0) ? L0 : (g == 1) ? L1 : (g == 2) ? L2 : L3;
    int K = (g & 1) ? 768 : 1024;
    const int M = ITEMS;
    int nIter = K >> 5;

    int tid = threadIdx.x;
    int wid = tid >> 5;
    int lane = tid & 31;
    int grp = lane >> 2;
    int tig = lane & 3;
    int warp_m = wid & 1;
    int warp_n = wid >> 1;
    int blockRow = blockIdx.x * 128;

    int a_row[4], a_kq[4], b_row[4], b_nq[4];
#pragma unroll
    for (int t = 0; t < 4; t++) {
        int idx = tid + t * 256;
        a_row[t] = idx >> 3;  a_kq[t] = (idx & 7) << 2;
        b_row[t] = idx >> 5;  b_nq[t] = (idx & 31) << 2;
    }

    auto load_stage = [&](int it, int buf) {
        int k0 = it << 5;
#pragma unroll
        for (int t = 0; t < 4; t++) {
            int gm = blockRow + a_row[t];
            uint32_t dst = (uint32_t)__cvta_generic_to_shared(&As[buf][a_row[t] * AS_STRIDE + a_kq[t]]);
            const float* src = A + (size_t)gm * K + k0 + a_kq[t];
            cp_async16(dst, src, (gm < M) ? 16 : 0);
        }
#pragma unroll
        for (int t = 0; t < 4; t++) {
            uint32_t dst = (uint32_t)__cvta_generic_to_shared(&Bs[buf][b_row[t] * BS_STRIDE + b_nq[t]]);
            const float* src = B + (size_t)(k0 + b_row[t]) * 128 + b_nq[t];
            cp_async16(dst, src, 16);
        }
        cp_commit();
    };

    float c[4][4][4];
#pragma unroll
    for (int mt = 0; mt < 4; mt++)
#pragma unroll
        for (int nt = 0; nt < 4; nt++)
#pragma unroll
            for (int f = 0; f < 4; f++) c[mt][nt][f] = 0.f;

    load_stage(0, 0);

    for (int it = 0; it < nIter; it++) {
        int cur = it & 1;
        if (it + 1 < nIter) {
            load_stage(it + 1, cur ^ 1);
            cp_wait<1>();
        } else {
            cp_wait<0>();
        }
        __syncthreads();

        uint32_t* as = As[cur];
        uint32_t* bs = Bs[cur];
#pragma unroll
        for (int ks = 0; ks < 4; ks++) {
            int kb = ks * 8;
            uint32_t a[4][4];
#pragma unroll
            for (int mt = 0; mt < 4; mt++) {
                int mb = warp_m * 64 + mt * 16;
                a[mt][0] = as[(mb + grp)     * AS_STRIDE + kb + tig];
                a[mt][1] = as[(mb + grp + 8) * AS_STRIDE + kb + tig];
                a[mt][2] = as[(mb + grp)     * AS_STRIDE + kb + tig + 4];
                a[mt][3] = as[(mb + grp + 8) * AS_STRIDE + kb + tig + 4];
            }
            uint32_t b[4][2];
#pragma unroll
            for (int nt = 0; nt < 4; nt++) {
                int nb = warp_n * 32 + nt * 8;
                b[nt][0] = bs[(kb + tig)     * BS_STRIDE + nb + grp];
                b[nt][1] = bs[(kb + tig + 4) * BS_STRIDE + nb + grp];
            }
#pragma unroll
            for (int mt = 0; mt < 4; mt++)
#pragma unroll
                for (int nt = 0; nt < 4; nt++)
                    mma_tf32(c[mt][nt], a[mt][0], a[mt][1], a[mt][2], a[mt][3],
                             b[nt][0], b[nt][1]);
        }
        __syncthreads();
    }

#pragma unroll
    for (int mt = 0; mt < 4; mt++) {
        int row0 = blockRow + warp_m * 64 + mt * 16 + grp;
        int row1 = row0 + 8;
#pragma unroll
        for (int nt = 0; nt < 4; nt++) {
            int col = warp_n * 32 + nt * 8 + 2 * tig;
            float v0 = c[mt][nt][0], v1 = c[mt][nt][1];
            float v2 = c[mt][nt][2], v3 = c[mt][nt][3];
            v0 = (v0 > 0.f) ? v0 : 0.2f * v0;
            v1 = (v1 > 0.f) ? v1 : 0.2f * v1;
            v2 = (v2 > 0.f) ? v2 : 0.2f * v2;
            v3 = (v3 > 0.f) ? v3 : 0.2f * v3;
            if (row0 < M) *(float2*)(L + (size_t)row0 * 128 + col) = make_float2(v0, v1);
            if (row1 < M) *(float2*)(L + (size_t)row1 * 128 + col) = make_float2(v2, v3);
        }
    }
}

// ---------------- helpers ----------------
__device__ __forceinline__ void store_h4(__half* base, size_t row, int lane, float4 v) {
    __half2 h0 = __floats2half2_rn(v.x, v.y);
    __half2 h1 = __floats2half2_rn(v.z, v.w);
    uint2 r;
    r.x = *reinterpret_cast<uint32_t*>(&h0);
    r.y = *reinterpret_cast<uint32_t*>(&h1);
    *((uint2*)(base + row * DIM) + lane) = r;
}

// combined weighted-l2norm: C = l2(w0*La0+w1*Lb0) + l2(w0*La1+w1*Lb1) -> fp16
__global__ void combine_l2norm_sum_kernel(const float* __restrict__ La0, const float* __restrict__ Lb0,
                                          const float* __restrict__ La1, const float* __restrict__ Lb1,
                                          const float* __restrict__ mw, __half* __restrict__ outC,
                                          int nrows)
{
    int wid = (blockIdx.x * blockDim.x + threadIdx.x) >> 5;
    int lane = threadIdx.x & 31;
    if (wid >= nrows) return;
    float m0 = mw[0], m1 = mw[1];
    float mx = fmaxf(m0, m1);
    float e0 = __expf(m0 - mx), e1 = __expf(m1 - mx);
    float w0 = e0 / (e0 + e1), w1 = e1 / (e0 + e1);
    size_t off = (size_t)wid * DIM + lane * 4;
    float4 a0 = *(const float4*)(La0 + off);
    float4 b0 = *(const float4*)(Lb0 + off);
    float4 a1 = *(const float4*)(La1 + off);
    float4 b1 = *(const float4*)(Lb1 + off);
    float4 v0, v1;
    v0.x = w0 * a0.x + w1 * b0.x;  v0.y = w0 * a0.y + w1 * b0.y;
    v0.z = w0 * a0.z + w1 * b0.z;  v0.w = w0 * a0.w + w1 * b0.w;
    v1.x = w0 * a1.x + w1 * b1.x;  v1.y = w0 * a1.y + w1 * b1.y;
    v1.z = w0 * a1.z + w1 * b1.z;  v1.w = w0 * a1.w + w1 * b1.w;
    float s0 = v0.x * v0.x + v0.y * v0.y + v0.z * v0.z + v0.w * v0.w;
    float s1 = v1.x * v1.x + v1.y * v1.y + v1.z * v1.z + v1.w * v1.w;
#pragma unroll
    for (int o = 16; o > 0; o >>= 1) {
        s0 += __shfl_xor_sync(0xffffffffu, s0, o);
        s1 += __shfl_xor_sync(0xffffffffu, s1, o);
    }
    float i0 = 1.f / fmaxf(sqrtf(s0), 1e-12f);
    float i1 = 1.f / fmaxf(sqrtf(s1), 1e-12f);
    float4 c;
    c.x = v0.x * i0 + v1.x * i1;
    c.y = v0.y * i0 + v1.y * i1;
    c.z = v0.z * i0 + v1.z * i1;
    c.w = v0.w * i0 + v1.w * i1;
    store_h4(outC, wid, lane, c);
}

// ---------------- half-warp LDG.128 CSR gather SpMM ----------------
template <bool FLAT>
__device__ __forceinline__ uint4 gfetch16(int col, int li,
                                          const __half* __restrict__ xU,
                                          const __half* __restrict__ xI) {
    const __half* x;
    if (FLAT) x = xU + (size_t)col * DIM;
    else x = (col < USERS) ? (xU + (size_t)col * DIM) : (xI + (size_t)(col - USERS) * DIM);
    return __ldg((const uint4*)x + li);
}
__device__ __forceinline__ void gacc8(float acc[8], float w, uint4 raw) {
    __half2* hp = reinterpret_cast<__half2*>(&raw);
#pragma unroll
    for (int q = 0; q < 4; q++) {
        float2 f = __half22float2(hp[q]);
        acc[2 * q]     += w * f.x;
        acc[2 * q + 1] += w * f.y;
    }
}
__device__ __forceinline__ void h8_to_f(uint4 raw, float out[8]) {
    __half2* hp = reinterpret_cast<__half2*>(&raw);
#pragma unroll
    for (int q = 0; q < 4; q++) {
        float2 f = __half22float2(hp[q]);
        out[2 * q] = f.x; out[2 * q + 1] = f.y;
    }
}

// warp-per-row body; lane = h*16+li covers cols [8li,8li+8) of edge (i+h).
template <bool FLAT>
__device__ __forceinline__ void spmm_row128(const float2* __restrict__ cv, int s, int e,
                                            int h, int li,
                                            const __half* __restrict__ xU,
                                            const __half* __restrict__ xI,
                                            float su, float si, float acc[8])
{
#pragma unroll
    for (int j = 0; j < 8; j++) acc[j] = 0.f;
    int i = s;
    for (; i + 8 <= e; i += 8) {
        float2 c[4]; uint4 raw[4]; float w[4];
#pragma unroll
        for (int u = 0; u < 4; u++) {
            c[u] = cv[i + 2 * u + h];
            int col = __float_as_int(c[u].x);
            w[u] = FLAT ? c[u].y : (c[u].y * ((col < USERS) ? su : si));
            raw[u] = gfetch16<FLAT>(col, li, xU, xI);
        }
#pragma unroll
        for (int u = 0; u < 4; u++) gacc8(acc, w[u], raw[u]);
    }
    for (; i + 2 <= e; i += 2) {
        float2 c = cv[i + h];
        int col = __float_as_int(c.x);
        float w = FLAT ? c.y : (c.y * ((col < USERS) ? su : si));
        gacc8(acc, w, gfetch16<FLAT>(col, li, xU, xI));
    }
    if (i < e && h == 0) {
        float2 c = cv[i];
        int col = __float_as_int(c.x);
        float w = FLAT ? c.y : (c.y * ((col < USERS) ? su : si));
        gacc8(acc, w, gfetch16<FLAT>(col, li, xU, xI));
    }
#pragma unroll
    for (int j = 0; j < 8; j++) acc[j] += __shfl_xor_sync(0xffffffffu, acc[j], 16);
}

__device__ __forceinline__ void store_row_f16(__half* __restrict__ outh, int row, int h, int li,
                                              const float acc[8]) {
    if (h) return;
    __half2 r0 = __floats2half2_rn(acc[0], acc[1]);
    __half2 r1 = __floats2half2_rn(acc[2], acc[3]);
    __half2 r2 = __floats2half2_rn(acc[4], acc[5]);
    __half2 r3 = __floats2half2_rn(acc[6], acc[7]);
    uint4 r;
    r.x = *reinterpret_cast<uint32_t*>(&r0);
    r.y = *reinterpret_cast<uint32_t*>(&r1);
    r.z = *reinterpret_cast<uint32_t*>(&r2);
    r.w = *reinterpret_cast<uint32_t*>(&r3);
    *((uint4*)(outh + (size_t)row * DIM) + li) = r;
}

// scaled spmm over row range [rowBegin, rowEnd), fp16-only out
__global__ void spmm_s16_kernel(const int* __restrict__ rowptr, const float2* __restrict__ cv,
                                const __half* __restrict__ xU, const __half* __restrict__ xI,
                                float su, float si, __half* __restrict__ outh,
                                int rowBegin, int rowEnd)
{
    int row = rowBegin + blockIdx.x * 8 + (threadIdx.x >> 5);
    int lane = threadIdx.x & 31;
    if (row >= rowEnd) return;
    int h = lane >> 4, li = lane & 15;
    float acc[8];
    spmm_row128<false>(cv, rowptr[row], rowptr[row + 1], h, li, xU, xI, su, si, acc);
    store_row_f16(outh, row, h, li, acc);
}

// Q pass + modal fusion over row range: acc = adj@[P_u; 2*iEmb]; modal = 0.5*acc+0.5*P+0.1*R
__global__ void spmm_qmodal_kernel(const int* __restrict__ rowptr, const float2* __restrict__ cv,
                                   const __half* __restrict__ hP, const __half* __restrict__ hI,
                                   const __half* __restrict__ hR, __half* __restrict__ modalh,
                                   int rowBegin, int rowEnd)
{
    int row = rowBegin + blockIdx.x * 8 + (threadIdx.x >> 5);
    int lane = threadIdx.x & 31;
    if (row >= rowEnd) return;
    int h = lane >> 4, li = lane & 15;
    float acc[8];
    spmm_row128<false>(cv, rowptr[row], rowptr[row + 1], h, li, hP, hI, 1.f, 2.f, acc);
    float p[8], r[8];
    h8_to_f(*((const uint4*)(hP + (size_t)row * DIM) + li), p);
    h8_to_f(*((const uint4*)(hR + (size_t)row * DIM) + li), r);
    float m[8];
#pragma unroll
    for (int j = 0; j < 8; j++) m[j] = 0.5f * acc[j] + 0.5f * p[j] + 0.1f * r[j];
    store_row_f16(modalh, row, h, li, m);
}

// GNN layer 1: A = adj @ modal (flat table), fp16 out
__global__ void spmm_flat16_kernel(const int* __restrict__ rowptr, const float2* __restrict__ cv,
                                   const __half* __restrict__ x, __half* __restrict__ outh)
{
    int row = blockIdx.x * 8 + (threadIdx.x >> 5);
    int lane = threadIdx.x & 31;
    if (row >= NTOT) return;
    int h = lane >> 4, li = lane & 15;
    float acc[8];
    spmm_row128<true>(cv, rowptr[row], rowptr[row + 1], h, li, x, nullptr, 1.f, 1.f, acc);
    store_row_f16(outh, row, h, li, acc);
}

// GNN layer-2 SpMM fused with final: out = modal + A + acc + (0.5/||modal||)*modal
__global__ void spmm_final_kernel(const int* __restrict__ rowptr, const float2* __restrict__ cv,
                                  const __half* __restrict__ hAx,
                                  const __half* __restrict__ modalh,
                                  float* __restrict__ out)
{
    int row = blockIdx.x * 8 + (threadIdx.x >> 5);
    int lane = threadIdx.x & 31;
    if (row >= NTOT) return;
    int h = lane >> 4, li = lane & 15;
    float acc[8];
    spmm_row128<true>(cv, rowptr[row], rowptr[row + 1], h, li, hAx, nullptr, 1.f, 1.f, acc);
    float m[8], a[8];
    h8_to_f(*((const uint4*)(modalh + (size_t)row * DIM) + li), m);
    h8_to_f(*((const uint4*)(hAx + (size_t)row * DIM) + li), a);
    float s = 0.f;
#pragma unroll
    for (int j = 0; j < 8; j++) s += m[j] * m[j];
#pragma unroll
    for (int o = 8; o > 0; o >>= 1) s += __shfl_xor_sync(0xffffffffu, s, o);
    float inv = 0.5f / fmaxf(sqrtf(s), 1e-12f);   // RIS_LAMBDA / norm
    float r[8];
#pragma unroll
    for (int j = 0; j < 8; j++) r[j] = m[j] + a[j] + acc[j] + inv * m[j];
    float4 v = h ? make_float4(r[4], r[5], r[6], r[7])
                 : make_float4(r[0], r[1], r[2], r[3]);
    *(float4*)(out + (size_t)row * DIM + li * 8 + h * 4) = v;
}

// ---------------- host ----------------
extern "C" void kernel_launch(void* const* d_in, const int* in_sizes, int n_in,
                              void* d_out, int out_size)
{
    const int*   adj_rows = (const int*)d_in[0];
    const int*   adj_cols = (const int*)d_in[1];
    const float* adj_vals = (const float*)d_in[2];
    const int*   id_rows  = (const int*)d_in[3];
    const int*   id_cols  = (const int*)d_in[4];
    const float* id_vals  = (const float*)d_in[5];
    const int*   ft_rows  = (const int*)d_in[6];
    const int*   ft_cols  = (const int*)d_in[7];
    const float* ft_vals  = (const float*)d_in[8];
    const float* uEmb     = (const float*)d_in[9];
    const float* iEmb     = (const float*)d_in[10];
    const float* img_emb  = (const float*)d_in[11];
    const float* img_id   = (const float*)d_in[12];
    const float* txt_emb  = (const float*)d_in[13];
    const float* txt_id   = (const float*)d_in[14];
    const float* img_tr   = (const float*)d_in[15];
    const float* img_id_tr= (const float*)d_in[16];
    const float* txt_tr   = (const float*)d_in[17];
    const float* txt_id_tr= (const float*)d_in[18];
    const float* mw       = (const float*)d_in[19];
    float* out = (float*)d_out;

    int E_adj = in_sizes[0];
    int E_id  = in_sizes[3];
    int E_ft  = in_sizes[6];
    int E_tot = E_adj + E_id + E_ft;

    float *pA, *pB;
    __half *hU, *hI, *hC, *hP, *hR, *hModal, *hA;
    float2 *cvAll;
    int *pRp, *pCounts, *pOffs, *pBsums;
    cudaGetSymbolAddress((void**)&pA,      g_tmpA);
    cudaGetSymbolAddress((void**)&pB,      g_tmpB);
    cudaGetSymbolAddress((void**)&hU,      g_h_u);
    cudaGetSymbolAddress((void**)&hI,      g_h_i);
    cudaGetSymbolAddress((void**)&hC,      g_h_C);
    cudaGetSymbolAddress((void**)&hP,      g_h_P);
    cudaGetSymbolAddress((void**)&hR,      g_h_R);
    cudaGetSymbolAddress((void**)&hModal,  g_h_modal);
    cudaGetSymbolAddress((void**)&hA,      g_h_A);
    cudaGetSymbolAddress((void**)&cvAll,   g_cv_all);
    cudaGetSymbolAddress((void**)&pRp,     g_rp);
    cudaGetSymbolAddress((void**)&pCounts, g_counts);
    cudaGetSymbolAddress((void**)&pOffs,   g_offs);
    cudaGetSymbolAddress((void**)&pBsums,  g_bsums);

    static cudaStream_t s1 = nullptr, s2 = nullptr;
    static cudaEvent_t evFork = nullptr, evGemmDone = nullptr, evPu = nullptr, evPi = nullptr;
    static bool inited = false;
    if (!inited) {
        cudaStreamCreateWithFlags(&s1, cudaStreamNonBlocking);
        cudaStreamCreateWithFlags(&s2, cudaStreamNonBlocking);
        cudaEventCreateWithFlags(&evFork, cudaEventDisableTiming);
        cudaEventCreateWithFlags(&evGemmDone, cudaEventDisableTiming);
        cudaEventCreateWithFlags(&evPu, cudaEventDisableTiming);
        cudaEventCreateWithFlags(&evPi, cudaEventDisableTiming);
        cudaFuncSetAttribute(gemm4_kernel, cudaFuncAttributeMaxDynamicSharedMemorySize,
                             GEMM_SMEM_BYTES);
        inited = true;
    }

    // GEMM lrelu buffers (consumed by combine_l2norm_sum)
    float* L_imgid = pA;
    float* L_txtid = pA + (size_t)ITEMS * DIM;
    float* L_img   = pB;
    float* L_txt   = pB + (size_t)ITEMS * DIM;

    // ---- fork: GEMM arm on s1, sparse arm on stream 0 ----
    cudaEventRecord(evFork, 0);
    cudaStreamWaitEvent(s1, evFork, 0);

    {
        dim3 ggrid((ITEMS + 127) / 128, 4);
        gemm4_kernel<<<ggrid, 256, GEMM_SMEM_BYTES, s1>>>(
            img_id, txt_id, img_emb, txt_emb,
            img_id_tr, txt_id_tr, img_tr, txt_tr,
            L_imgid, L_txtid, L_img, L_txt);
        int cl_blocks = (ITEMS * 32 + 255) / 256;
        combine_l2norm_sum_kernel<<<cl_blocks, 256, 0, s1>>>(L_imgid, L_txtid, L_img, L_txt,
                                                             mw, hC, ITEMS);
        cudaEventRecord(evGemmDone, s1);
    }

    // stream 0: batched CSR build (seg0=adj, seg1=id+ft merged)
    {
        int n = 2 * NSEG;
        int nb = (n + SCAN_BLOCK - 1) / SCAN_BLOCK;
        zero_int_kernel<<<(n + 255) / 256, 256>>>(pCounts, n);
        hist3_kernel<<<(E_tot + 255) / 256, 256>>>(adj_rows, id_rows, ft_rows,
                                                   E_adj, E_id, E_ft, pCounts);
        scan1_kernel<<<nb, SCAN_BLOCK>>>(pCounts, pRp, pBsums, n);
        scan2_kernel<<<1, NB_MAX>>>(pBsums, nb);
        scan3_kernel<<<nb, SCAN_BLOCK>>>(pRp, pBsums, pOffs, n);
        scatter3_kernel<<<(E_tot + 255) / 256, 256>>>(adj_rows, adj_cols, adj_vals,
                                                      id_rows, id_cols, id_vals,
                                                      ft_rows, ft_cols, ft_vals,
                                                      E_adj, E_id, E_ft, pOffs, cvAll);
    }
    const int* rpAdj = pRp;
    const int* rpMrg = pRp + NSEG;

    // stream 0: fp16 input tables + merged R pass (overlaps GEMM arm)
    {
        int n4u = USERS * DIM / 4;
        f2h2_kernel<<<(2 * n4u + 255) / 256, 256>>>((const float4*)uEmb, (const float4*)iEmb,
                                                    (uint2*)hU, (uint2*)hI, n4u);
    }
    int blocksAll   = (NTOT + 7) / 8;
    int blocksUsers = (USERS + 7) / 8;
    int blocksItems = (ITEMS + 7) / 8;
    // R = (id_mat + ft_mat) @ [u; i]
    spmm_s16_kernel<<<blocksAll, 256>>>(rpMrg, cvAll, hU, hI, 1.f, 1.f, hR, 0, NTOT);

    // ---- join: P pass needs hC from GEMM arm ----
    cudaStreamWaitEvent(0, evGemmDone, 0);

    // P_users = adj@[2u; C] (rows < USERS)
    spmm_s16_kernel<<<blocksUsers, 256>>>(rpAdj, cvAll, hU, hC, 2.f, 1.f, hP, 0, USERS);
    cudaEventRecord(evPu, 0);

    // s2: P_items (rows >= USERS), concurrent with Q_users on stream 0
    cudaStreamWaitEvent(s2, evPu, 0);
    spmm_s16_kernel<<<blocksItems, 256, 0, s2>>>(rpAdj, cvAll, hU, hC, 2.f, 1.f, hP, USERS, NTOT);
    cudaEventRecord(evPi, s2);

    // stream 0: Q_users (needs only P_users: gathers P for cols<USERS, epilogue row<USERS)
    spmm_qmodal_kernel<<<blocksUsers, 256>>>(rpAdj, cvAll, hP, hI, hR, hModal, 0, USERS);

    // stream 0: Q_items needs P_items epilogue -> wait s2
    cudaStreamWaitEvent(0, evPi, 0);
    spmm_qmodal_kernel<<<blocksItems, 256>>>(rpAdj, cvAll, hP, hI, hR, hModal, USERS, NTOT);

    // GNN layer 1: A = adj@modal (flat, fp16 only)
    spmm_flat16_kernel<<<blocksAll, 256>>>(rpAdj, cvAll, hModal, hA);
    // GNN layer 2 fused with final (flat)
    spmm_final_kernel<<<blocksAll, 256>>>(rpAdj, cvAll, hA, hModal, out);

    (void)n_in; (void)out_size;
}

// round 16
// speedup vs baseline: 1.0229x; 1.0229x over previous
#include <cuda_runtime.h>
#include <cuda_fp16.h>
#include <cstdint>
#include <cstddef>

#define USERS 50000
#define ITEMS 50000
#define NTOT  100000
#define DIM   128
#define EMAX  1700000
#define SCAN_BLOCK 1024
#define NB_MAX 512
#define NSEG  (NTOT + 1)

// ---------------- scratch (device globals; allocation-free) ----------------
__device__ float g_tmpA  [(size_t)NTOT * DIM];   // GEMM L0/L1
__device__ float g_tmpB  [(size_t)NTOT * DIM];   // GEMM L2/L3

// fp16 tables (16B-aligned for uint4 loads)
__device__ __align__(16) __half g_h_u     [(size_t)USERS * DIM];
__device__ __align__(16) __half g_h_i     [(size_t)ITEMS * DIM];
__device__ __align__(16) __half g_h_C     [(size_t)ITEMS * DIM];   // l2(allID)+l2(allFeat)
__device__ __align__(16) __half g_h_P     [(size_t)NTOT * DIM];    // Id+Ft
__device__ __align__(16) __half g_h_R     [(size_t)NTOT * DIM];    // IdAdj+FtAdj
__device__ __align__(16) __half g_h_modal [(size_t)NTOT * DIM];
__device__ __align__(16) __half g_h_A     [(size_t)NTOT * DIM];

// batched CSR: seg0 = adj, seg1 = id+ft merged
__device__ float2 g_cv_all [3 * EMAX];
__device__ int    g_rp     [2 * NSEG];
__device__ int    g_counts [2 * NSEG];
__device__ int    g_offs   [2 * NSEG];
__device__ int    g_bsums  [NB_MAX];

// ---------------- small utility kernels ----------------
__global__ void zero_int_kernel(int* __restrict__ p, int n) {
    int i = blockIdx.x * blockDim.x + threadIdx.x;
    if (i < n) p[i] = 0;
}

// both embedding tables -> fp16 in one launch
__global__ void f2h2_kernel(const float4* __restrict__ inU, const float4* __restrict__ inI,
                            uint2* __restrict__ outU, uint2* __restrict__ outI, int n4each) {
    int i = blockIdx.x * blockDim.x + threadIdx.x;
    if (i >= 2 * n4each) return;
    const float4* in = (i < n4each) ? inU : inI;
    uint2* o = (i < n4each) ? outU : outI;
    int j = (i < n4each) ? i : i - n4each;
    float4 v = in[j];
    __half2 h0 = __floats2half2_rn(v.x, v.y);
    __half2 h1 = __floats2half2_rn(v.z, v.w);
    uint2 r;
    r.x = *reinterpret_cast<uint32_t*>(&h0);
    r.y = *reinterpret_cast<uint32_t*>(&h1);
    o[j] = r;
}

// ---------------- batched counting sort (2 segments: adj | id+ft merged) ------------
__global__ void hist3_kernel(const int* __restrict__ r0, const int* __restrict__ r1,
                             const int* __restrict__ r2, int n0, int n1, int n2,
                             int* __restrict__ counts) {
    int i = blockIdx.x * blockDim.x + threadIdx.x;
    int nt = n0 + n1 + n2;
    if (i >= nt) return;
    int row, seg;
    if (i < n0)            { seg = 0; row = r0[i]; }
    else if (i < n0 + n1)  { seg = 1; row = r1[i - n0]; }
    else                   { seg = 1; row = r2[i - n0 - n1]; }   // merged with id
    atomicAdd(&counts[seg * NSEG + row], 1);
}

__global__ void scan1_kernel(const int* __restrict__ counts, int* __restrict__ rowptr,
                             int* __restrict__ bsums, int n) {
    __shared__ int sh[SCAN_BLOCK];
    int g = blockIdx.x * SCAN_BLOCK + threadIdx.x;
    int v = (g < n) ? counts[g] : 0;
    sh[threadIdx.x] = v;
    __syncthreads();
    for (int off = 1; off < SCAN_BLOCK; off <<= 1) {
        int t = (threadIdx.x >= off) ? sh[threadIdx.x - off] : 0;
        __syncthreads();
        sh[threadIdx.x] += t;
        __syncthreads();
    }
    if (g < n) rowptr[g] = sh[threadIdx.x] - v;   // exclusive
    if (threadIdx.x == SCAN_BLOCK - 1) bsums[blockIdx.x] = sh[threadIdx.x];
}

__global__ void scan2_kernel(int* __restrict__ bsums, int nb) {
    __shared__ int sh[NB_MAX];
    int v = (threadIdx.x < nb) ? bsums[threadIdx.x] : 0;
    sh[threadIdx.x] = v;
    __syncthreads();
    for (int off = 1; off < NB_MAX; off <<= 1) {
        int t = (threadIdx.x >= off) ? sh[threadIdx.x - off] : 0;
        __syncthreads();
        sh[threadIdx.x] += t;
        __syncthreads();
    }
    if (threadIdx.x < nb) bsums[threadIdx.x] = sh[threadIdx.x] - v;  // exclusive
}

__global__ void scan3_kernel(int* __restrict__ rowptr, const int* __restrict__ bsums,
                             int* __restrict__ offs, int n) {
    int g = blockIdx.x * SCAN_BLOCK + threadIdx.x;
    if (g < n) {
        int v = rowptr[g] + bsums[blockIdx.x];
        rowptr[g] = v;
        offs[g] = v;
    }
}

__global__ void scatter3_kernel(const int* __restrict__ r0, const int* __restrict__ c0, const float* __restrict__ v0,
                                const int* __restrict__ r1, const int* __restrict__ c1, const float* __restrict__ v1,
                                const int* __restrict__ r2, const int* __restrict__ c2, const float* __restrict__ v2,
                                int n0, int n1, int n2,
                                int* __restrict__ offs, float2* __restrict__ cv) {
    int i = blockIdx.x * blockDim.x + threadIdx.x;
    int nt = n0 + n1 + n2;
    if (i >= nt) return;
    int row, seg, col; float val;
    if (i < n0)           { seg = 0; int j = i;            row = r0[j]; col = c0[j]; val = v0[j]; }
    else if (i < n0 + n1) { seg = 1; int j = i - n0;       row = r1[j]; col = c1[j]; val = v1[j]; }
    else                  { seg = 1; int j = i - n0 - n1;  row = r2[j]; col = c2[j]; val = v2[j]; }
    int pos = atomicAdd(&offs[seg * NSEG + row], 1);
    cv[pos] = make_float2(__int_as_float(col), val);
}

// ---------------- tf32 tensor-core GEMM with 2-stage cp.async double buffering --------
__device__ __forceinline__ void mma_tf32(float c[4], uint32_t a0, uint32_t a1,
                                         uint32_t a2, uint32_t a3,
                                         uint32_t b0, uint32_t b1) {
    asm volatile(
        "mma.sync.aligned.m16n8k8.row.col.f32.tf32.tf32.f32 "
        "{%0,%1,%2,%3}, {%4,%5,%6,%7}, {%8,%9}, {%0,%1,%2,%3};"
        : "+f"(c[0]), "+f"(c[1]), "+f"(c[2]), "+f"(c[3])
        : "r"(a0), "r"(a1), "r"(a2), "r"(a3), "r"(b0), "r"(b1));
}

__device__ __forceinline__ void cp_async16(uint32_t smem_addr, const void* gsrc, int src_bytes) {
    asm volatile("cp.async.cg.shared.global [%0], [%1], 16, %2;"
                 :: "r"(smem_addr), "l"(gsrc), "r"(src_bytes));
}
__device__ __forceinline__ void cp_commit() {
    asm volatile("cp.async.commit_group;");
}
template <int N>
__device__ __forceinline__ void cp_wait() {
    asm volatile("cp.async.wait_group %0;" :: "n"(N));
}

#define AS_STRIDE 36
#define BS_STRIDE 132
#define AS_WORDS (128 * AS_STRIDE)
#define BS_WORDS (32 * BS_STRIDE)
#define GEMM_SMEM_WORDS (2 * (AS_WORDS + BS_WORDS))
#define GEMM_SMEM_BYTES (GEMM_SMEM_WORDS * 4)

__global__ __launch_bounds__(256, 2) void gemm4_kernel(
    const float* __restrict__ A0, const float* __restrict__ A1,
    const float* __restrict__ A2, const float* __restrict__ A3,
    const float* __restrict__ B0, const float* __restrict__ B1,
    const float* __restrict__ B2, const float* __restrict__ B3,
    float* __restrict__ L0, float* __restrict__ L1,
    float* __restrict__ L2, float* __restrict__ L3)
{
    extern __shared__ uint32_t smem[];
    uint32_t* As[2] = { smem, smem + AS_WORDS };
    uint32_t* Bs[2] = { smem + 2 * AS_WORDS, smem + 2 * AS_WORDS + BS_WORDS };

    int g = blockIdx.y;
    const float* A = (g == 0) ? A0 : (g == 1) ? A1 : (g == 2) ? A2 : A3;
    const float* B = (g == 0) ? B0 : (g == 1) ? B1 : (g == 2) ? B2 : B3;
    float*       L = (g == 0) ? L0 : (g == 1) ? L1 : (g == 2) ? L2 : L3;
    int K = (g & 1) ? 768 : 1024;
    const int M = ITEMS;
    int nIter = K >> 5;

    int tid = threadIdx.x;
    int wid = tid >> 5;
    int lane = tid & 31;
    int grp = lane >> 2;
    int tig = lane & 3;
    int warp_m = wid & 1;
    int warp_n = wid >> 1;
    int blockRow = blockIdx.x * 128;

    int a_row[4], a_kq[4], b_row[4], b_nq[4];
#pragma unroll
    for (int t = 0; t < 4; t++) {
        int idx = tid + t * 256;
        a_row[t] = idx >> 3;  a_kq[t] = (idx & 7) << 2;
        b_row[t] = idx >> 5;  b_nq[t] = (idx & 31) << 2;
    }

    auto load_stage = [&](int it, int buf) {
        int k0 = it << 5;
#pragma unroll
        for (int t = 0; t < 4; t++) {
            int gm = blockRow + a_row[t];
            uint32_t dst = (uint32_t)__cvta_generic_to_shared(&As[buf][a_row[t] * AS_STRIDE + a_kq[t]]);
            const float* src = A + (size_t)gm * K + k0 + a_kq[t];
            cp_async16(dst, src, (gm < M) ? 16 : 0);
        }
#pragma unroll
        for (int t = 0; t < 4; t++) {
            uint32_t dst = (uint32_t)__cvta_generic_to_shared(&Bs[buf][b_row[t] * BS_STRIDE + b_nq[t]]);
            const float* src = B + (size_t)(k0 + b_row[t]) * 128 + b_nq[t];
            cp_async16(dst, src, 16);
        }
        cp_commit();
    };

    float c[4][4][4];
#pragma unroll
    for (int mt = 0; mt < 4; mt++)
#pragma unroll
        for (int nt = 0; nt < 4; nt++)
#pragma unroll
            for (int f = 0; f < 4; f++) c[mt][nt][f] = 0.f;

    load_stage(0, 0);

    for (int it = 0; it < nIter; it++) {
        int cur = it & 1;
        if (it + 1 < nIter) {
            load_stage(it + 1, cur ^ 1);
            cp_wait<1>();
        } else {
            cp_wait<0>();
        }
        __syncthreads();

        uint32_t* as = As[cur];
        uint32_t* bs = Bs[cur];
#pragma unroll
        for (int ks = 0; ks < 4; ks++) {
            int kb = ks * 8;
            uint32_t a[4][4];
#pragma unroll
            for (int mt = 0; mt < 4; mt++) {
                int mb = warp_m * 64 + mt * 16;
                a[mt][0] = as[(mb + grp)     * AS_STRIDE + kb + tig];
                a[mt][1] = as[(mb + grp + 8) * AS_STRIDE + kb + tig];
                a[mt][2] = as[(mb + grp)     * AS_STRIDE + kb + tig + 4];
                a[mt][3] = as[(mb + grp + 8) * AS_STRIDE + kb + tig + 4];
            }
            uint32_t b[4][2];
#pragma unroll
            for (int nt = 0; nt < 4; nt++) {
                int nb = warp_n * 32 + nt * 8;
                b[nt][0] = bs[(kb + tig)     * BS_STRIDE + nb + grp];
                b[nt][1] = bs[(kb + tig + 4) * BS_STRIDE + nb + grp];
            }
#pragma unroll
            for (int mt = 0; mt < 4; mt++)
#pragma unroll
                for (int nt = 0; nt < 4; nt++)
                    mma_tf32(c[mt][nt], a[mt][0], a[mt][1], a[mt][2], a[mt][3],
                             b[nt][0], b[nt][1]);
        }
        __syncthreads();
    }

#pragma unroll
    for (int mt = 0; mt < 4; mt++) {
        int row0 = blockRow + warp_m * 64 + mt * 16 + grp;
        int row1 = row0 + 8;
#pragma unroll
        for (int nt = 0; nt < 4; nt++) {
            int col = warp_n * 32 + nt * 8 + 2 * tig;
            float v0 = c[mt][nt][0], v1 = c[mt][nt][1];
            float v2 = c[mt][nt][2], v3 = c[mt][nt][3];
            v0 = (v0 > 0.f) ? v0 : 0.2f * v0;
            v1 = (v1 > 0.f) ? v1 : 0.2f * v1;
            v2 = (v2 > 0.f) ? v2 : 0.2f * v2;
            v3 = (v3 > 0.f) ? v3 : 0.2f * v3;
            if (row0 < M) *(float2*)(L + (size_t)row0 * 128 + col) = make_float2(v0, v1);
            if (row1 < M) *(float2*)(L + (size_t)row1 * 128 + col) = make_float2(v2, v3);
        }
    }
}

// ---------------- helpers ----------------
__device__ __forceinline__ void store_h4(__half* base, size_t row, int lane, float4 v) {
    __half2 h0 = __floats2half2_rn(v.x, v.y);
    __half2 h1 = __floats2half2_rn(v.z, v.w);
    uint2 r;
    r.x = *reinterpret_cast<uint32_t*>(&h0);
    r.y = *reinterpret_cast<uint32_t*>(&h1);
    *((uint2*)(base + row * DIM) + lane) = r;
}

// combined weighted-l2norm: C = l2(w0*La0+w1*Lb0) + l2(w0*La1+w1*Lb1) -> fp16
__global__ void combine_l2norm_sum_kernel(const float* __restrict__ La0, const float* __restrict__ Lb0,
                                          const float* __restrict__ La1, const float* __restrict__ Lb1,
                                          const float* __restrict__ mw, __half* __restrict__ outC,
                                          int nrows)
{
    int wid = (blockIdx.x * blockDim.x + threadIdx.x) >> 5;
    int lane = threadIdx.x & 31;
    if (wid >= nrows) return;
    float m0 = mw[0], m1 = mw[1];
    float mx = fmaxf(m0, m1);
    float e0 = __expf(m0 - mx), e1 = __expf(m1 - mx);
    float w0 = e0 / (e0 + e1), w1 = e1 / (e0 + e1);
    size_t off = (size_t)wid * DIM + lane * 4;
    float4 a0 = *(const float4*)(La0 + off);
    float4 b0 = *(const float4*)(Lb0 + off);
    float4 a1 = *(const float4*)(La1 + off);
    float4 b1 = *(const float4*)(Lb1 + off);
    float4 v0, v1;
    v0.x = w0 * a0.x + w1 * b0.x;  v0.y = w0 * a0.y + w1 * b0.y;
    v0.z = w0 * a0.z + w1 * b0.z;  v0.w = w0 * a0.w + w1 * b0.w;
    v1.x = w0 * a1.x + w1 * b1.x;  v1.y = w0 * a1.y + w1 * b1.y;
    v1.z = w0 * a1.z + w1 * b1.z;  v1.w = w0 * a1.w + w1 * b1.w;
    float s0 = v0.x * v0.x + v0.y * v0.y + v0.z * v0.z + v0.w * v0.w;
    float s1 = v1.x * v1.x + v1.y * v1.y + v1.z * v1.z + v1.w * v1.w;
#pragma unroll
    for (int o = 16; o > 0; o >>= 1) {
        s0 += __shfl_xor_sync(0xffffffffu, s0, o);
        s1 += __shfl_xor_sync(0xffffffffu, s1, o);
    }
    float i0 = 1.f / fmaxf(sqrtf(s0), 1e-12f);
    float i1 = 1.f / fmaxf(sqrtf(s1), 1e-12f);
    float4 c;
    c.x = v0.x * i0 + v1.x * i1;
    c.y = v0.y * i0 + v1.y * i1;
    c.z = v0.z * i0 + v1.z * i1;
    c.w = v0.w * i0 + v1.w * i1;
    store_h4(outC, wid, lane, c);
}

// ---------------- half-warp LDG.128 CSR gather SpMM ----------------
template <bool FLAT>
__device__ __forceinline__ uint4 gfetch16(int col, int li,
                                          const __half* __restrict__ xU,
                                          const __half* __restrict__ xI) {
    const __half* x;
    if (FLAT) x = xU + (size_t)col * DIM;
    else x = (col < USERS) ? (xU + (size_t)col * DIM) : (xI + (size_t)(col - USERS) * DIM);
    return __ldg((const uint4*)x + li);
}
__device__ __forceinline__ void gacc8(float acc[8], float w, uint4 raw) {
    __half2* hp = reinterpret_cast<__half2*>(&raw);
#pragma unroll
    for (int q = 0; q < 4; q++) {
        float2 f = __half22float2(hp[q]);
        acc[2 * q]     += w * f.x;
        acc[2 * q + 1] += w * f.y;
    }
}
__device__ __forceinline__ void h8_to_f(uint4 raw, float out[8]) {
    __half2* hp = reinterpret_cast<__half2*>(&raw);
#pragma unroll
    for (int q = 0; q < 4; q++) {
        float2 f = __half22float2(hp[q]);
        out[2 * q] = f.x; out[2 * q + 1] = f.y;
    }
}

// warp-per-row body; lane = h*16+li covers cols [8li,8li+8) of edge (i+h).
template <bool FLAT>
__device__ __forceinline__ void spmm_row128(const float2* __restrict__ cv, int s, int e,
                                            int h, int li,
                                            const __half* __restrict__ xU,
                                            const __half* __restrict__ xI,
                                            float su, float si, float acc[8])
{
#pragma unroll
    for (int j = 0; j < 8; j++) acc[j] = 0.f;
    int i = s;
    for (; i + 8 <= e; i += 8) {
        float2 c[4]; uint4 raw[4]; float w[4];
#pragma unroll
        for (int u = 0; u < 4; u++) {
            c[u] = cv[i + 2 * u + h];
            int col = __float_as_int(c[u].x);
            w[u] = FLAT ? c[u].y : (c[u].y * ((col < USERS) ? su : si));
            raw[u] = gfetch16<FLAT>(col, li, xU, xI);
        }
#pragma unroll
        for (int u = 0; u < 4; u++) gacc8(acc, w[u], raw[u]);
    }
    for (; i + 2 <= e; i += 2) {
        float2 c = cv[i + h];
        int col = __float_as_int(c.x);
        float w = FLAT ? c.y : (c.y * ((col < USERS) ? su : si));
        gacc8(acc, w, gfetch16<FLAT>(col, li, xU, xI));
    }
    if (i < e && h == 0) {
        float2 c = cv[i];
        int col = __float_as_int(c.x);
        float w = FLAT ? c.y : (c.y * ((col < USERS) ? su : si));
        gacc8(acc, w, gfetch16<FLAT>(col, li, xU, xI));
    }
#pragma unroll
    for (int j = 0; j < 8; j++) acc[j] += __shfl_xor_sync(0xffffffffu, acc[j], 16);
}

__device__ __forceinline__ void store_row_f16(__half* __restrict__ outh, int row, int h, int li,
                                              const float acc[8]) {
    if (h) return;
    __half2 r0 = __floats2half2_rn(acc[0], acc[1]);
    __half2 r1 = __floats2half2_rn(acc[2], acc[3]);
    __half2 r2 = __floats2half2_rn(acc[4], acc[5]);
    __half2 r3 = __floats2half2_rn(acc[6], acc[7]);
    uint4 r;
    r.x = *reinterpret_cast<uint32_t*>(&r0);
    r.y = *reinterpret_cast<uint32_t*>(&r1);
    r.z = *reinterpret_cast<uint32_t*>(&r2);
    r.w = *reinterpret_cast<uint32_t*>(&r3);
    *((uint4*)(outh + (size_t)row * DIM) + li) = r;
}

// scaled spmm, fp16-only out (R pass, P pass)
__global__ void spmm_s16_kernel(const int* __restrict__ rowptr, const float2* __restrict__ cv,
                                const __half* __restrict__ xU, const __half* __restrict__ xI,
                                float su, float si, __half* __restrict__ outh)
{
    int row = blockIdx.x * 8 + (threadIdx.x >> 5);
    int lane = threadIdx.x & 31;
    if (row >= NTOT) return;
    int h = lane >> 4, li = lane & 15;
    float acc[8];
    spmm_row128<false>(cv, rowptr[row], rowptr[row + 1], h, li, xU, xI, su, si, acc);
    store_row_f16(outh, row, h, li, acc);
}

// Q pass + modal fusion: acc = adj@[P_u; 2*iEmb]; modal = 0.5*acc + 0.5*P + 0.1*R (fp16 only)
__global__ void spmm_qmodal_kernel(const int* __restrict__ rowptr, const float2* __restrict__ cv,
                                   const __half* __restrict__ hP, const __half* __restrict__ hI,
                                   const __half* __restrict__ hR, __half* __restrict__ modalh)
{
    int row = blockIdx.x * 8 + (threadIdx.x >> 5);
    int lane = threadIdx.x & 31;
    if (row >= NTOT) return;
    int h = lane >> 4, li = lane & 15;
    float acc[8];
    spmm_row128<false>(cv, rowptr[row], rowptr[row + 1], h, li, hP, hI, 1.f, 2.f, acc);
    float p[8], r[8];
    h8_to_f(*((const uint4*)(hP + (size_t)row * DIM) + li), p);
    h8_to_f(*((const uint4*)(hR + (size_t)row * DIM) + li), r);
    float m[8];
#pragma unroll
    for (int j = 0; j < 8; j++) m[j] = 0.5f * acc[j] + 0.5f * p[j] + 0.1f * r[j];
    store_row_f16(modalh, row, h, li, m);
}

// GNN layer 1: A = adj @ modal (flat table), fp16 out
__global__ void spmm_flat16_kernel(const int* __restrict__ rowptr, const float2* __restrict__ cv,
                                   const __half* __restrict__ x, __half* __restrict__ outh)
{
    int row = blockIdx.x * 8 + (threadIdx.x >> 5);
    int lane = threadIdx.x & 31;
    if (row >= NTOT) return;
    int h = lane >> 4, li = lane & 15;
    float acc[8];
    spmm_row128<true>(cv, rowptr[row], rowptr[row + 1], h, li, x, nullptr, 1.f, 1.f, acc);
    store_row_f16(outh, row, h, li, acc);
}

// GNN layer-2 SpMM fused with final: out = modal + A + acc + (0.5/||modal||)*modal
__global__ void spmm_final_kernel(const int* __restrict__ rowptr, const float2* __restrict__ cv,
                                  const __half* __restrict__ hAx,
                                  const __half* __restrict__ modalh,
                                  float* __restrict__ out)
{
    int row = blockIdx.x * 8 + (threadIdx.x >> 5);
    int lane = threadIdx.x & 31;
    if (row >= NTOT) return;
    int h = lane >> 4, li = lane & 15;
    float acc[8];
    spmm_row128<true>(cv, rowptr[row], rowptr[row + 1], h, li, hAx, nullptr, 1.f, 1.f, acc);
    float m[8], a[8];
    h8_to_f(*((const uint4*)(modalh + (size_t)row * DIM) + li), m);
    h8_to_f(*((const uint4*)(hAx + (size_t)row * DIM) + li), a);
    float s = 0.f;
#pragma unroll
    for (int j = 0; j < 8; j++) s += m[j] * m[j];
#pragma unroll
    for (int o = 8; o > 0; o >>= 1) s += __shfl_xor_sync(0xffffffffu, s, o);
    float inv = 0.5f / fmaxf(sqrtf(s), 1e-12f);   // RIS_LAMBDA / norm
    float r[8];
#pragma unroll
    for (int j = 0; j < 8; j++) r[j] = m[j] + a[j] + acc[j] + inv * m[j];
    float4 v = h ? make_float4(r[4], r[5], r[6], r[7])
                 : make_float4(r[0], r[1], r[2], r[3]);
    *(float4*)(out + (size_t)row * DIM + li * 8 + h * 4) = v;
}

// ---------------- host ----------------
extern "C" void kernel_launch(void* const* d_in, const int* in_sizes, int n_in,
                              void* d_out, int out_size)
{
    const int*   adj_rows = (const int*)d_in[0];
    const int*   adj_cols = (const int*)d_in[1];
    const float* adj_vals = (const float*)d_in[2];
    const int*   id_rows  = (const int*)d_in[3];
    const int*   id_cols  = (const int*)d_in[4];
    const float* id_vals  = (const float*)d_in[5];
    const int*   ft_rows  = (const int*)d_in[6];
    const int*   ft_cols  = (const int*)d_in[7];
    const float* ft_vals  = (const float*)d_in[8];
    const float* uEmb     = (const float*)d_in[9];
    const float* iEmb     = (const float*)d_in[10];
    const float* img_emb  = (const float*)d_in[11];
    const float* img_id   = (const float*)d_in[12];
    const float* txt_emb  = (const float*)d_in[13];
    const float* txt_id   = (const float*)d_in[14];
    const float* img_tr   = (const float*)d_in[15];
    const float* img_id_tr= (const float*)d_in[16];
    const float* txt_tr   = (const float*)d_in[17];
    const float* txt_id_tr= (const float*)d_in[18];
    const float* mw       = (const float*)d_in[19];
    float* out = (float*)d_out;

    int E_adj = in_sizes[0];
    int E_id  = in_sizes[3];
    int E_ft  = in_sizes[6];
    int E_tot = E_adj + E_id + E_ft;

    float *pA, *pB;
    __half *hU, *hI, *hC, *hP, *hR, *hModal, *hA;
    float2 *cvAll;
    int *pRp, *pCounts, *pOffs, *pBsums;
    cudaGetSymbolAddress((void**)&pA,      g_tmpA);
    cudaGetSymbolAddress((void**)&pB,      g_tmpB);
    cudaGetSymbolAddress((void**)&hU,      g_h_u);
    cudaGetSymbolAddress((void**)&hI,      g_h_i);
    cudaGetSymbolAddress((void**)&hC,      g_h_C);
    cudaGetSymbolAddress((void**)&hP,      g_h_P);
    cudaGetSymbolAddress((void**)&hR,      g_h_R);
    cudaGetSymbolAddress((void**)&hModal,  g_h_modal);
    cudaGetSymbolAddress((void**)&hA,      g_h_A);
    cudaGetSymbolAddress((void**)&cvAll,   g_cv_all);
    cudaGetSymbolAddress((void**)&pRp,     g_rp);
    cudaGetSymbolAddress((void**)&pCounts, g_counts);
    cudaGetSymbolAddress((void**)&pOffs,   g_offs);
    cudaGetSymbolAddress((void**)&pBsums,  g_bsums);

    static cudaStream_t s1 = nullptr, s2 = nullptr;
    static cudaEvent_t evFork = nullptr, evGemmDone = nullptr, evSparseReady = nullptr, evR = nullptr;
    static bool inited = false;
    if (!inited) {
        cudaStreamCreateWithFlags(&s1, cudaStreamNonBlocking);
        cudaStreamCreateWithFlags(&s2, cudaStreamNonBlocking);
        cudaEventCreateWithFlags(&evFork, cudaEventDisableTiming);
        cudaEventCreateWithFlags(&evGemmDone, cudaEventDisableTiming);
        cudaEventCreateWithFlags(&evSparseReady, cudaEventDisableTiming);
        cudaEventCreateWithFlags(&evR, cudaEventDisableTiming);
        cudaFuncSetAttribute(gemm4_kernel, cudaFuncAttributeMaxDynamicSharedMemorySize,
                             GEMM_SMEM_BYTES);
        inited = true;
    }

    // GEMM lrelu buffers (consumed by combine_l2norm_sum)
    float* L_imgid = pA;
    float* L_txtid = pA + (size_t)ITEMS * DIM;
    float* L_img   = pB;
    float* L_txt   = pB + (size_t)ITEMS * DIM;

    // ---- fork: GEMM arm on s1, sparse arm on stream 0 ----
    cudaEventRecord(evFork, 0);
    cudaStreamWaitEvent(s1, evFork, 0);

    {
        dim3 ggrid((ITEMS + 127) / 128, 4);
        gemm4_kernel<<<ggrid, 256, GEMM_SMEM_BYTES, s1>>>(
            img_id, txt_id, img_emb, txt_emb,
            img_id_tr, txt_id_tr, img_tr, txt_tr,
            L_imgid, L_txtid, L_img, L_txt);
        int cl_blocks = (ITEMS * 32 + 255) / 256;
        combine_l2norm_sum_kernel<<<cl_blocks, 256, 0, s1>>>(L_imgid, L_txtid, L_img, L_txt,
                                                             mw, hC, ITEMS);
        cudaEventRecord(evGemmDone, s1);
    }

    // stream 0: batched CSR build (seg0=adj, seg1=id+ft merged)
    {
        int n = 2 * NSEG;
        int nb = (n + SCAN_BLOCK - 1) / SCAN_BLOCK;
        zero_int_kernel<<<(n + 255) / 256, 256>>>(pCounts, n);
        hist3_kernel<<<(E_tot + 255) / 256, 256>>>(adj_rows, id_rows, ft_rows,
                                                   E_adj, E_id, E_ft, pCounts);
        scan1_kernel<<<nb, SCAN_BLOCK>>>(pCounts, pRp, pBsums, n);
        scan2_kernel<<<1, NB_MAX>>>(pBsums, nb);
        scan3_kernel<<<nb, SCAN_BLOCK>>>(pRp, pBsums, pOffs, n);
        scatter3_kernel<<<(E_tot + 255) / 256, 256>>>(adj_rows, adj_cols, adj_vals,
                                                      id_rows, id_cols, id_vals,
                                                      ft_rows, ft_cols, ft_vals,
                                                      E_adj, E_id, E_ft, pOffs, cvAll);
    }
    const int* rpAdj = pRp;
    const int* rpMrg = pRp + NSEG;

    // stream 0: fp16 input tables (overlaps GEMM arm)
    {
        int n4u = USERS * DIM / 4;
        f2h2_kernel<<<(2 * n4u + 255) / 256, 256>>>((const float4*)uEmb, (const float4*)iEmb,
                                                    (uint2*)hU, (uint2*)hI, n4u);
    }
    cudaEventRecord(evSparseReady, 0);

    int spmm_blocks = (NTOT + 7) / 8;

    // s2: R = (id_mat + ft_mat) @ [u; i] — off the critical path; consumed only by Q epilogue
    cudaStreamWaitEvent(s2, evSparseReady, 0);
    spmm_s16_kernel<<<spmm_blocks, 256, 0, s2>>>(rpMrg, cvAll, hU, hI, 1.f, 1.f, hR);
    cudaEventRecord(evR, s2);

    // ---- stream 0: join with GEMM arm, then P ----
    cudaStreamWaitEvent(0, evGemmDone, 0);

    // P = Id+Ft = adj @ [2*u ; C]  (concurrent with R on s2)
    spmm_s16_kernel<<<spmm_blocks, 256>>>(rpAdj, cvAll, hU, hC, 2.f, 1.f, hP);

    // Q needs R's output in its epilogue
    cudaStreamWaitEvent(0, evR, 0);
    spmm_qmodal_kernel<<<spmm_blocks, 256>>>(rpAdj, cvAll, hP, hI, hR, hModal);
    // GNN layer 1: A = adj@modal (flat, fp16 only)
    spmm_flat16_kernel<<<spmm_blocks, 256>>>(rpAdj, cvAll, hModal, hA);
    // GNN layer 2 fused with final (flat)
    spmm_final_kernel<<<spmm_blocks, 256>>>(rpAdj, cvAll, hA, hModal, out);

    (void)n_in; (void)out_size;
}